// round 5
// baseline (speedup 1.0000x reference)
#include <cuda_runtime.h>
#include <math.h>

#define HID 8
#define KSIZE 5
#define KK (KSIZE * KSIZE * KSIZE)   // 125

// Scratch for hidden activations (h_pre then h after ELU). 16B-aligned: we hit
// it with red.global.add.v4.f32 (16-byte wide reduction) and float4 loads.
#define MAX_NODES 50000
__device__ __align__(16) float g_h[MAX_NODES * HID];

__device__ __forceinline__ void red_add_v4(float* addr, float4 v) {
    asm volatile("red.global.add.v4.f32 [%0], {%1,%2,%3,%4};"
                 :: "l"(addr), "f"(v.x), "f"(v.y), "f"(v.z), "f"(v.w) : "memory");
}
__device__ __forceinline__ void red_add_f32(float* addr, float v) {
    asm volatile("red.global.add.f32 [%0], %1;" :: "l"(addr), "f"(v) : "memory");
}

__device__ __forceinline__ float elu1(float v) {
    return v > 0.f ? v : expm1f(v);
}

// Per-edge spline basis: base cell index + 8 trilinear corner weights.
struct Basis {
    int base;
    float w[8];
};

__device__ __forceinline__ Basis make_basis(float p0, float p1, float p2) {
    float pos0 = p0 * (KSIZE - 1), pos1 = p1 * (KSIZE - 1), pos2 = p2 * (KSIZE - 1);
    float f0 = fminf(fmaxf(floorf(pos0), 0.f), (float)(KSIZE - 2));
    float f1 = fminf(fmaxf(floorf(pos1), 0.f), (float)(KSIZE - 2));
    float f2 = fminf(fmaxf(floorf(pos2), 0.f), (float)(KSIZE - 2));
    float r0 = pos0 - f0, r1 = pos1 - f1, r2 = pos2 - f2;
    float u0 = 1.f - r0, u1 = 1.f - r1, u2 = 1.f - r2;
    Basis b;
    b.base = (int)f0 + KSIZE * (int)f1 + KSIZE * KSIZE * (int)f2;
    b.w[0] = u0 * u1 * u2;
    b.w[1] = r0 * u1 * u2;
    b.w[2] = u0 * r1 * u2;
    b.w[3] = r0 * r1 * u2;
    b.w[4] = u0 * u1 * r2;
    b.w[5] = r0 * u1 * r2;
    b.w[6] = u0 * r1 * r2;
    b.w[7] = r0 * r1 * r2;
    return b;
}

__constant__ int c_offs[8] = {0, 1, KSIZE, KSIZE + 1,
                              KSIZE * KSIZE, KSIZE * KSIZE + 1,
                              KSIZE * KSIZE + KSIZE, KSIZE * KSIZE + KSIZE + 1};

// K1: h_pre[n][o] = x[n] * root1[o] + bias1[o]
__global__ void k_init_h(const float* __restrict__ x,
                         const float* __restrict__ root1,
                         const float* __restrict__ bias1, int n_nodes) {
    int i = blockIdx.x * blockDim.x + threadIdx.x;
    if (i < n_nodes * HID) {
        int n = i >> 3, o = i & 7;
        g_h[i] = x[n] * root1[o] + bias1[o];
    }
}

// K2: layer-1 edge messages: g_h[dst] += x[src] * sum_b basis_b * W1[kidx_b][0][:]
__global__ void k_edge1(const int* __restrict__ ei,
                        const float* __restrict__ pseudo,
                        const float* __restrict__ x,
                        const float* __restrict__ W1, int n_edges) {
    __shared__ __align__(16) float sW[KK * HID];
    for (int i = threadIdx.x; i < KK * HID; i += blockDim.x) sW[i] = W1[i];
    __syncthreads();

    int e = blockIdx.x * blockDim.x + threadIdx.x;
    if (e >= n_edges) return;

    int src = ei[e];
    int dst = ei[n_edges + e];
    float p0 = pseudo[3 * e], p1 = pseudo[3 * e + 1], p2 = pseudo[3 * e + 2];
    Basis bs = make_basis(p0, p1, p2);

    float4 a0 = make_float4(0.f, 0.f, 0.f, 0.f);
    float4 a1 = make_float4(0.f, 0.f, 0.f, 0.f);
#pragma unroll
    for (int b = 0; b < 8; b++) {
        const float4* wp = (const float4*)&sW[(bs.base + c_offs[b]) * HID];
        float4 w0 = wp[0], w1 = wp[1];
        float wb = bs.w[b];
        a0.x += wb * w0.x; a0.y += wb * w0.y; a0.z += wb * w0.z; a0.w += wb * w0.w;
        a1.x += wb * w1.x; a1.y += wb * w1.y; a1.z += wb * w1.z; a1.w += wb * w1.w;
    }
    float xj = __ldg(&x[src]);
    a0.x *= xj; a0.y *= xj; a0.z *= xj; a0.w *= xj;
    a1.x *= xj; a1.y *= xj; a1.z *= xj; a1.w *= xj;

    red_add_v4(&g_h[dst * HID], a0);
    red_add_v4(&g_h[dst * HID + 4], a1);
}

// K3: h = elu(h_pre) in place; out_pre[n] = h . root2 + bias2
__global__ void k_act1(const float* __restrict__ root2,
                       const float* __restrict__ bias2,
                       float* __restrict__ out, int n_nodes) {
    int n = blockIdx.x * blockDim.x + threadIdx.x;
    if (n >= n_nodes) return;
    float acc = bias2[0];
#pragma unroll
    for (int o = 0; o < HID; o++) {
        float v = g_h[n * HID + o];
        v = elu1(v);
        g_h[n * HID + o] = v;
        acc += v * __ldg(&root2[o]);
    }
    out[n] = acc;
}

// K4: layer-2 edge messages: out[dst] += h[src] . (sum_b basis_b * W2[kidx_b][:][0])
__global__ void k_edge2(const int* __restrict__ ei,
                        const float* __restrict__ pseudo,
                        const float* __restrict__ W2,
                        float* __restrict__ out, int n_edges) {
    __shared__ __align__(16) float sW[KK * HID];
    for (int i = threadIdx.x; i < KK * HID; i += blockDim.x) sW[i] = W2[i];
    __syncthreads();

    int e = blockIdx.x * blockDim.x + threadIdx.x;
    if (e >= n_edges) return;

    int src = ei[e];
    int dst = ei[n_edges + e];
    float p0 = pseudo[3 * e], p1 = pseudo[3 * e + 1], p2 = pseudo[3 * e + 2];
    Basis bs = make_basis(p0, p1, p2);

    float4 a0 = make_float4(0.f, 0.f, 0.f, 0.f);
    float4 a1 = make_float4(0.f, 0.f, 0.f, 0.f);
#pragma unroll
    for (int b = 0; b < 8; b++) {
        const float4* wp = (const float4*)&sW[(bs.base + c_offs[b]) * HID];
        float4 w0 = wp[0], w1 = wp[1];
        float wb = bs.w[b];
        a0.x += wb * w0.x; a0.y += wb * w0.y; a0.z += wb * w0.z; a0.w += wb * w0.w;
        a1.x += wb * w1.x; a1.y += wb * w1.y; a1.z += wb * w1.z; a1.w += wb * w1.w;
    }

    const float4* hp = (const float4*)&g_h[src * HID];
    float4 h0 = hp[0], h1 = hp[1];
    float val = a0.x * h0.x + a0.y * h0.y + a0.z * h0.z + a0.w * h0.w
              + a1.x * h1.x + a1.y * h1.y + a1.z * h1.z + a1.w * h1.w;

    red_add_f32(&out[dst], val);
}

// K5: out = elu(out) in place
__global__ void k_act2(float* __restrict__ out, int n_nodes) {
    int n = blockIdx.x * blockDim.x + threadIdx.x;
    if (n < n_nodes) out[n] = elu1(out[n]);
}

extern "C" void kernel_launch(void* const* d_in, const int* in_sizes, int n_in,
                              void* d_out, int out_size) {
    const float* x      = (const float*)d_in[0];
    const int*   ei     = (const int*)d_in[1];      // int32! (JAX x64 disabled)
    const float* pseudo = (const float*)d_in[2];
    const float* W1     = (const float*)d_in[3];
    const float* root1  = (const float*)d_in[4];
    const float* bias1  = (const float*)d_in[5];
    const float* W2     = (const float*)d_in[6];
    const float* root2  = (const float*)d_in[7];
    const float* bias2  = (const float*)d_in[8];
    float* out = (float*)d_out;

    int n_nodes = in_sizes[0];        // x is [N, 1]
    int n_edges = in_sizes[1] / 2;    // edge_index is [2, E]

    const int T = 256;
    k_init_h<<<(n_nodes * HID + T - 1) / T, T>>>(x, root1, bias1, n_nodes);
    k_edge1<<<(n_edges + T - 1) / T, T>>>(ei, pseudo, x, W1, n_edges);
    k_act1<<<(n_nodes + T - 1) / T, T>>>(root2, bias2, out, n_nodes);
    k_edge2<<<(n_edges + T - 1) / T, T>>>(ei, pseudo, W2, out, n_edges);
    k_act2<<<(n_nodes + T - 1) / T, T>>>(out, n_nodes);
}

// round 7
// speedup vs baseline: 1.2284x; 1.2284x over previous
#include <cuda_runtime.h>
#include <math.h>

#define HID 8
#define KSIZE 5
#define KK (KSIZE * KSIZE * KSIZE)   // 125
#define WSTRIDE 10                   // padded floats per cell: 16 bank groups, 8B-aligned

#define MAX_NODES 50000
__device__ __align__(16) float g_h[MAX_NODES * HID];

__device__ __forceinline__ void red_add_v4(float* addr, float4 v) {
    asm volatile("red.global.add.v4.f32 [%0], {%1,%2,%3,%4};"
                 :: "l"(addr), "f"(v.x), "f"(v.y), "f"(v.z), "f"(v.w) : "memory");
}
__device__ __forceinline__ void red_add_f32(float* addr, float v) {
    asm volatile("red.global.add.f32 [%0], %1;" :: "l"(addr), "f"(v) : "memory");
}

__device__ __forceinline__ float elu1(float v) {
    return v > 0.f ? v : expm1f(v);
}

struct Basis {
    int base;
    float w[8];
};

__device__ __forceinline__ Basis make_basis(float p0, float p1, float p2) {
    float pos0 = p0 * (KSIZE - 1), pos1 = p1 * (KSIZE - 1), pos2 = p2 * (KSIZE - 1);
    float f0 = fminf(fmaxf(floorf(pos0), 0.f), (float)(KSIZE - 2));
    float f1 = fminf(fmaxf(floorf(pos1), 0.f), (float)(KSIZE - 2));
    float f2 = fminf(fmaxf(floorf(pos2), 0.f), (float)(KSIZE - 2));
    float r0 = pos0 - f0, r1 = pos1 - f1, r2 = pos2 - f2;
    float u0 = 1.f - r0, u1 = 1.f - r1, u2 = 1.f - r2;
    Basis b;
    b.base = (int)f0 + KSIZE * (int)f1 + KSIZE * KSIZE * (int)f2;
    b.w[0] = u0 * u1 * u2;
    b.w[1] = r0 * u1 * u2;
    b.w[2] = u0 * r1 * u2;
    b.w[3] = r0 * r1 * u2;
    b.w[4] = u0 * u1 * r2;
    b.w[5] = r0 * u1 * r2;
    b.w[6] = u0 * r1 * r2;
    b.w[7] = r0 * r1 * r2;
    return b;
}

__constant__ int c_offs[8] = {0, 1, KSIZE, KSIZE + 1,
                              KSIZE * KSIZE, KSIZE * KSIZE + 1,
                              KSIZE * KSIZE + KSIZE, KSIZE * KSIZE + KSIZE + 1};

// Gathered weight combine from padded smem table: out[8] = sum_b w_b * W[cell_b][:]
__device__ __forceinline__ void combine_w(const float* sW, const Basis& bs,
                                          float2& a01, float2& a23, float2& a45, float2& a67) {
    a01 = make_float2(0.f, 0.f);
    a23 = make_float2(0.f, 0.f);
    a45 = make_float2(0.f, 0.f);
    a67 = make_float2(0.f, 0.f);
#pragma unroll
    for (int b = 0; b < 8; b++) {
        const float2* wp = (const float2*)&sW[(bs.base + c_offs[b]) * WSTRIDE];
        float2 w0 = wp[0], w1 = wp[1], w2 = wp[2], w3 = wp[3];
        float wb = bs.w[b];
        a01.x += wb * w0.x; a01.y += wb * w0.y;
        a23.x += wb * w1.x; a23.y += wb * w1.y;
        a45.x += wb * w2.x; a45.y += wb * w2.y;
        a67.x += wb * w3.x; a67.y += wb * w3.y;
    }
}

// K1: h_pre[n][o] = x[n] * root1[o] + bias1[o]
__global__ void k_init_h(const float* __restrict__ x,
                         const float* __restrict__ root1,
                         const float* __restrict__ bias1, int n_nodes) {
    int n = blockIdx.x * blockDim.x + threadIdx.x;
    if (n >= n_nodes) return;
    float xv = x[n];
    float4 r0 = *(const float4*)&root1[0];
    float4 r1 = *(const float4*)&root1[4];
    float4 b0 = *(const float4*)&bias1[0];
    float4 b1 = *(const float4*)&bias1[4];
    float4* hp = (float4*)&g_h[n * HID];
    hp[0] = make_float4(xv * r0.x + b0.x, xv * r0.y + b0.y, xv * r0.z + b0.z, xv * r0.w + b0.w);
    hp[1] = make_float4(xv * r1.x + b1.x, xv * r1.y + b1.y, xv * r1.z + b1.z, xv * r1.w + b1.w);
}

// K2: layer-1, 4 edges per thread
__global__ void k_edge1(const int* __restrict__ ei,
                        const float* __restrict__ pseudo,
                        const float* __restrict__ x,
                        const float* __restrict__ W1, int n_edges) {
    __shared__ __align__(16) float sW[KK * WSTRIDE];
    for (int i = threadIdx.x; i < KK * WSTRIDE; i += blockDim.x) {
        int cell = i / WSTRIDE, o = i % WSTRIDE;
        sW[i] = (o < HID) ? W1[cell * HID + o] : 0.f;
    }
    __syncthreads();

    int e0 = (blockIdx.x * blockDim.x + threadIdx.x) * 4;
    if (e0 >= n_edges) return;

    // all edges in [e0, e0+4) valid because n_edges % 4 handled below
    bool full = (e0 + 4 <= n_edges);
    int4 src4, dst4;
    float4 P0, P1, P2;
    if (full) {
        src4 = *(const int4*)&ei[e0];
        dst4 = *(const int4*)&ei[n_edges + e0];
        const float4* pp = (const float4*)&pseudo[3 * e0];
        P0 = pp[0]; P1 = pp[1]; P2 = pp[2];
    } else {
        int s[4] = {0,0,0,0}, d[4] = {0,0,0,0};
        float p[12] = {0};
        for (int k = 0; k < 4 && e0 + k < n_edges; k++) {
            s[k] = ei[e0 + k]; d[k] = ei[n_edges + e0 + k];
            p[3*k] = pseudo[3*(e0+k)]; p[3*k+1] = pseudo[3*(e0+k)+1]; p[3*k+2] = pseudo[3*(e0+k)+2];
        }
        src4 = make_int4(s[0], s[1], s[2], s[3]);
        dst4 = make_int4(d[0], d[1], d[2], d[3]);
        P0 = make_float4(p[0], p[1], p[2], p[3]);
        P1 = make_float4(p[4], p[5], p[6], p[7]);
        P2 = make_float4(p[8], p[9], p[10], p[11]);
    }

    // batch gathers up-front for MLP
    float xj0 = __ldg(&x[src4.x]);
    float xj1 = __ldg(&x[src4.y]);
    float xj2 = __ldg(&x[src4.z]);
    float xj3 = __ldg(&x[src4.w]);

    float pe[4][3] = {{P0.x, P0.y, P0.z}, {P0.w, P1.x, P1.y},
                      {P1.z, P1.w, P2.x}, {P2.y, P2.z, P2.w}};
    float xj[4] = {xj0, xj1, xj2, xj3};
    int dst[4] = {dst4.x, dst4.y, dst4.z, dst4.w};

#pragma unroll
    for (int k = 0; k < 4; k++) {
        if (e0 + k >= n_edges) break;
        Basis bs = make_basis(pe[k][0], pe[k][1], pe[k][2]);
        float2 a01, a23, a45, a67;
        combine_w(sW, bs, a01, a23, a45, a67);
        float xv = xj[k];
        red_add_v4(&g_h[dst[k] * HID],
                   make_float4(xv * a01.x, xv * a01.y, xv * a23.x, xv * a23.y));
        red_add_v4(&g_h[dst[k] * HID + 4],
                   make_float4(xv * a45.x, xv * a45.y, xv * a67.x, xv * a67.y));
    }
}

// K3: h = elu(h_pre) in place; out_pre[n] = h . root2 + bias2
__global__ void k_act1(const float* __restrict__ root2,
                       const float* __restrict__ bias2,
                       float* __restrict__ out, int n_nodes) {
    int n = blockIdx.x * blockDim.x + threadIdx.x;
    if (n >= n_nodes) return;
    float4* hp = (float4*)&g_h[n * HID];
    float4 h0 = hp[0], h1 = hp[1];
    h0.x = elu1(h0.x); h0.y = elu1(h0.y); h0.z = elu1(h0.z); h0.w = elu1(h0.w);
    h1.x = elu1(h1.x); h1.y = elu1(h1.y); h1.z = elu1(h1.z); h1.w = elu1(h1.w);
    hp[0] = h0; hp[1] = h1;
    float4 r0 = *(const float4*)&root2[0];
    float4 r1 = *(const float4*)&root2[4];
    float acc = bias2[0]
              + h0.x * r0.x + h0.y * r0.y + h0.z * r0.z + h0.w * r0.w
              + h1.x * r1.x + h1.y * r1.y + h1.z * r1.z + h1.w * r1.w;
    out[n] = acc;
}

// K4: layer-2, 4 edges per thread
__global__ void k_edge2(const int* __restrict__ ei,
                        const float* __restrict__ pseudo,
                        const float* __restrict__ W2,
                        float* __restrict__ out, int n_edges) {
    __shared__ __align__(16) float sW[KK * WSTRIDE];
    for (int i = threadIdx.x; i < KK * WSTRIDE; i += blockDim.x) {
        int cell = i / WSTRIDE, o = i % WSTRIDE;
        sW[i] = (o < HID) ? W2[cell * HID + o] : 0.f;
    }
    __syncthreads();

    int e0 = (blockIdx.x * blockDim.x + threadIdx.x) * 4;
    if (e0 >= n_edges) return;

    bool full = (e0 + 4 <= n_edges);
    int4 src4, dst4;
    float4 P0, P1, P2;
    if (full) {
        src4 = *(const int4*)&ei[e0];
        dst4 = *(const int4*)&ei[n_edges + e0];
        const float4* pp = (const float4*)&pseudo[3 * e0];
        P0 = pp[0]; P1 = pp[1]; P2 = pp[2];
    } else {
        int s[4] = {0,0,0,0}, d[4] = {0,0,0,0};
        float p[12] = {0};
        for (int k = 0; k < 4 && e0 + k < n_edges; k++) {
            s[k] = ei[e0 + k]; d[k] = ei[n_edges + e0 + k];
            p[3*k] = pseudo[3*(e0+k)]; p[3*k+1] = pseudo[3*(e0+k)+1]; p[3*k+2] = pseudo[3*(e0+k)+2];
        }
        src4 = make_int4(s[0], s[1], s[2], s[3]);
        dst4 = make_int4(d[0], d[1], d[2], d[3]);
        P0 = make_float4(p[0], p[1], p[2], p[3]);
        P1 = make_float4(p[4], p[5], p[6], p[7]);
        P2 = make_float4(p[8], p[9], p[10], p[11]);
    }

    // batch the 8 gather loads up-front (4 edges x 32B)
    int src[4] = {src4.x, src4.y, src4.z, src4.w};
    float4 hh[4][2];
#pragma unroll
    for (int k = 0; k < 4; k++) {
        const float4* hp = (const float4*)&g_h[src[k] * HID];
        hh[k][0] = hp[0];
        hh[k][1] = hp[1];
    }

    float pe[4][3] = {{P0.x, P0.y, P0.z}, {P0.w, P1.x, P1.y},
                      {P1.z, P1.w, P2.x}, {P2.y, P2.z, P2.w}};
    int dst[4] = {dst4.x, dst4.y, dst4.z, dst4.w};

#pragma unroll
    for (int k = 0; k < 4; k++) {
        if (e0 + k >= n_edges) break;
        Basis bs = make_basis(pe[k][0], pe[k][1], pe[k][2]);
        float2 a01, a23, a45, a67;
        combine_w(sW, bs, a01, a23, a45, a67);
        float4 h0 = hh[k][0], h1 = hh[k][1];
        float val = a01.x * h0.x + a01.y * h0.y + a23.x * h0.z + a23.y * h0.w
                  + a45.x * h1.x + a45.y * h1.y + a67.x * h1.z + a67.y * h1.w;
        red_add_f32(&out[dst[k]], val);
    }
}

// K5: out = elu(out) in place
__global__ void k_act2(float* __restrict__ out, int n_nodes) {
    int n = blockIdx.x * blockDim.x + threadIdx.x;
    if (n < n_nodes) out[n] = elu1(out[n]);
}

extern "C" void kernel_launch(void* const* d_in, const int* in_sizes, int n_in,
                              void* d_out, int out_size) {
    const float* x      = (const float*)d_in[0];
    const int*   ei     = (const int*)d_in[1];      // int32 (JAX x64 disabled)
    const float* pseudo = (const float*)d_in[2];
    const float* W1     = (const float*)d_in[3];
    const float* root1  = (const float*)d_in[4];
    const float* bias1  = (const float*)d_in[5];
    const float* W2     = (const float*)d_in[6];
    const float* root2  = (const float*)d_in[7];
    const float* bias2  = (const float*)d_in[8];
    float* out = (float*)d_out;

    int n_nodes = in_sizes[0];
    int n_edges = in_sizes[1] / 2;

    const int T = 256;
    int eb = (n_edges + 4 * T - 1) / (4 * T);
    k_init_h<<<(n_nodes + T - 1) / T, T>>>(x, root1, bias1, n_nodes);
    k_edge1<<<eb, T>>>(ei, pseudo, x, W1, n_edges);
    k_act1<<<(n_nodes + T - 1) / T, T>>>(root2, bias2, out, n_nodes);
    k_edge2<<<eb, T>>>(ei, pseudo, W2, out, n_edges);
    k_act2<<<(n_nodes + T - 1) / T, T>>>(out, n_nodes);
}

// round 8
// speedup vs baseline: 1.2776x; 1.0401x over previous
#include <cuda_runtime.h>
#include <math.h>

#define HID 8
#define KSIZE 5
#define KK (KSIZE * KSIZE * KSIZE)   // 125
#define WSTRIDE 10                   // padded floats per cell -> spread bank groups

#define MAX_NODES 50000
__device__ __align__(16) float g_h[MAX_NODES * HID];

__device__ __forceinline__ void red_add_v4(float* addr, float4 v) {
    asm volatile("red.global.add.v4.f32 [%0], {%1,%2,%3,%4};"
                 :: "l"(addr), "f"(v.x), "f"(v.y), "f"(v.z), "f"(v.w) : "memory");
}
__device__ __forceinline__ void red_add_f32(float* addr, float v) {
    asm volatile("red.global.add.f32 [%0], %1;" :: "l"(addr), "f"(v) : "memory");
}

__device__ __forceinline__ float elu1(float v) {
    return v > 0.f ? v : expm1f(v);
}

struct Basis {
    int base;
    float w[8];
};

__device__ __forceinline__ Basis make_basis(float p0, float p1, float p2) {
    float pos0 = p0 * (KSIZE - 1), pos1 = p1 * (KSIZE - 1), pos2 = p2 * (KSIZE - 1);
    float f0 = fminf(fmaxf(floorf(pos0), 0.f), (float)(KSIZE - 2));
    float f1 = fminf(fmaxf(floorf(pos1), 0.f), (float)(KSIZE - 2));
    float f2 = fminf(fmaxf(floorf(pos2), 0.f), (float)(KSIZE - 2));
    float r0 = pos0 - f0, r1 = pos1 - f1, r2 = pos2 - f2;
    float u0 = 1.f - r0, u1 = 1.f - r1, u2 = 1.f - r2;
    Basis b;
    b.base = (int)f0 + KSIZE * (int)f1 + KSIZE * KSIZE * (int)f2;
    b.w[0] = u0 * u1 * u2;
    b.w[1] = r0 * u1 * u2;
    b.w[2] = u0 * r1 * u2;
    b.w[3] = r0 * r1 * u2;
    b.w[4] = u0 * u1 * r2;
    b.w[5] = r0 * u1 * r2;
    b.w[6] = u0 * r1 * r2;
    b.w[7] = r0 * r1 * r2;
    return b;
}

__constant__ int c_offs[8] = {0, 1, KSIZE, KSIZE + 1,
                              KSIZE * KSIZE, KSIZE * KSIZE + 1,
                              KSIZE * KSIZE + KSIZE, KSIZE * KSIZE + KSIZE + 1};

// Half-combine: this lane's 4 channels (half in {0,1}) of sum_b w_b * W[cell_b][:]
__device__ __forceinline__ float4 combine_half(const float* sW, const Basis& bs, int half) {
    float4 a = make_float4(0.f, 0.f, 0.f, 0.f);
    const float* sWh = sW + half * 4;
#pragma unroll
    for (int b = 0; b < 8; b++) {
        const float2* wp = (const float2*)&sWh[(bs.base + c_offs[b]) * WSTRIDE];
        float2 w0 = wp[0], w1 = wp[1];
        float wb = bs.w[b];
        a.x += wb * w0.x; a.y += wb * w0.y;
        a.z += wb * w1.x; a.w += wb * w1.y;
    }
    return a;
}

__device__ __forceinline__ void load_smem_w(float* sW, const float* W) {
    for (int i = threadIdx.x; i < KK * WSTRIDE; i += blockDim.x) {
        int cell = i / WSTRIDE, o = i - cell * WSTRIDE;
        sW[i] = (o < HID) ? W[cell * HID + o] : 0.f;
    }
    __syncthreads();
}

// K1: h_pre[n][o] = x[n] * root1[o] + bias1[o]
__global__ void k_init_h(const float* __restrict__ x,
                         const float* __restrict__ root1,
                         const float* __restrict__ bias1, int n_nodes) {
    int n = blockIdx.x * blockDim.x + threadIdx.x;
    if (n >= n_nodes) return;
    float xv = x[n];
    float4 r0 = *(const float4*)&root1[0];
    float4 r1 = *(const float4*)&root1[4];
    float4 b0 = *(const float4*)&bias1[0];
    float4 b1 = *(const float4*)&bias1[4];
    float4* hp = (float4*)&g_h[n * HID];
    hp[0] = make_float4(xv * r0.x + b0.x, xv * r0.y + b0.y, xv * r0.z + b0.z, xv * r0.w + b0.w);
    hp[1] = make_float4(xv * r1.x + b1.x, xv * r1.y + b1.y, xv * r1.z + b1.z, xv * r1.w + b1.w);
}

// K2: layer-1, pair-cooperative: 2 lanes per edge, 2 edges per pair.
// lane half=t&1 handles channels [half*4, half*4+4).
__global__ void k_edge1(const int* __restrict__ ei,
                        const float* __restrict__ pseudo,
                        const float* __restrict__ x,
                        const float* __restrict__ W1, int n_edges) {
    __shared__ __align__(16) float sW[KK * WSTRIDE];
    load_smem_w(sW, W1);

    int t = blockIdx.x * blockDim.x + threadIdx.x;
    int p = t >> 1, half = t & 1;
    int e0 = p * 2;
    if (e0 >= n_edges) return;
    bool two = (e0 + 1 < n_edges);

    int2 s2, d2;
    float pe[2][3];
    if (two) {
        s2 = *(const int2*)&ei[e0];
        d2 = *(const int2*)&ei[n_edges + e0];
        float2 q0 = *(const float2*)&pseudo[3 * e0];
        float2 q1 = *(const float2*)&pseudo[3 * e0 + 2];
        float2 q2 = *(const float2*)&pseudo[3 * e0 + 4];
        pe[0][0] = q0.x; pe[0][1] = q0.y; pe[0][2] = q1.x;
        pe[1][0] = q1.y; pe[1][1] = q2.x; pe[1][2] = q2.y;
    } else {
        s2 = make_int2(ei[e0], 0);
        d2 = make_int2(ei[n_edges + e0], 0);
        pe[0][0] = pseudo[3 * e0]; pe[0][1] = pseudo[3 * e0 + 1]; pe[0][2] = pseudo[3 * e0 + 2];
        pe[1][0] = pe[1][1] = pe[1][2] = 0.f;
    }

    float xj0 = __ldg(&x[s2.x]);
    float xj1 = two ? __ldg(&x[s2.y]) : 0.f;

    {
        Basis bs = make_basis(pe[0][0], pe[0][1], pe[0][2]);
        float4 a = combine_half(sW, bs, half);
        red_add_v4(&g_h[d2.x * HID + half * 4],
                   make_float4(xj0 * a.x, xj0 * a.y, xj0 * a.z, xj0 * a.w));
    }
    if (two) {
        Basis bs = make_basis(pe[1][0], pe[1][1], pe[1][2]);
        float4 a = combine_half(sW, bs, half);
        red_add_v4(&g_h[d2.y * HID + half * 4],
                   make_float4(xj1 * a.x, xj1 * a.y, xj1 * a.z, xj1 * a.w));
    }
}

// K3: h = elu(h_pre) in place; out_pre[n] = h . root2 + bias2
__global__ void k_act1(const float* __restrict__ root2,
                       const float* __restrict__ bias2,
                       float* __restrict__ out, int n_nodes) {
    int n = blockIdx.x * blockDim.x + threadIdx.x;
    if (n >= n_nodes) return;
    float4* hp = (float4*)&g_h[n * HID];
    float4 h0 = hp[0], h1 = hp[1];
    h0.x = elu1(h0.x); h0.y = elu1(h0.y); h0.z = elu1(h0.z); h0.w = elu1(h0.w);
    h1.x = elu1(h1.x); h1.y = elu1(h1.y); h1.z = elu1(h1.z); h1.w = elu1(h1.w);
    hp[0] = h0; hp[1] = h1;
    float4 r0 = *(const float4*)&root2[0];
    float4 r1 = *(const float4*)&root2[4];
    float acc = bias2[0]
              + h0.x * r0.x + h0.y * r0.y + h0.z * r0.z + h0.w * r0.w
              + h1.x * r1.x + h1.y * r1.y + h1.z * r1.z + h1.w * r1.w;
    out[n] = acc;
}

// K4: layer-2, pair-cooperative. Each lane: 16B gather + 4-chan dot; shfl-xor pair sum; lane0 REDs.
__global__ void k_edge2(const int* __restrict__ ei,
                        const float* __restrict__ pseudo,
                        const float* __restrict__ W2,
                        float* __restrict__ out, int n_edges) {
    __shared__ __align__(16) float sW[KK * WSTRIDE];
    load_smem_w(sW, W2);

    int t = blockIdx.x * blockDim.x + threadIdx.x;
    int p = t >> 1, half = t & 1;
    int e0 = p * 2;
    if (e0 >= n_edges) return;
    bool two = (e0 + 1 < n_edges);

    int2 s2, d2;
    float pe[2][3];
    if (two) {
        s2 = *(const int2*)&ei[e0];
        d2 = *(const int2*)&ei[n_edges + e0];
        float2 q0 = *(const float2*)&pseudo[3 * e0];
        float2 q1 = *(const float2*)&pseudo[3 * e0 + 2];
        float2 q2 = *(const float2*)&pseudo[3 * e0 + 4];
        pe[0][0] = q0.x; pe[0][1] = q0.y; pe[0][2] = q1.x;
        pe[1][0] = q1.y; pe[1][1] = q2.x; pe[1][2] = q2.y;
    } else {
        s2 = make_int2(ei[e0], 0);
        d2 = make_int2(ei[n_edges + e0], 0);
        pe[0][0] = pseudo[3 * e0]; pe[0][1] = pseudo[3 * e0 + 1]; pe[0][2] = pseudo[3 * e0 + 2];
        pe[1][0] = pe[1][1] = pe[1][2] = 0.f;
    }

    // 16B half-gathers, batched for MLP
    float4 h0 = *(const float4*)&g_h[s2.x * HID + half * 4];
    float4 h1 = two ? *(const float4*)&g_h[s2.y * HID + half * 4]
                    : make_float4(0.f, 0.f, 0.f, 0.f);

    unsigned mask = __activemask();
    {
        Basis bs = make_basis(pe[0][0], pe[0][1], pe[0][2]);
        float4 a = combine_half(sW, bs, half);
        float v = a.x * h0.x + a.y * h0.y + a.z * h0.z + a.w * h0.w;
        v += __shfl_xor_sync(mask, v, 1);
        if (half == 0) red_add_f32(&out[d2.x], v);
    }
    if (two) {
        Basis bs = make_basis(pe[1][0], pe[1][1], pe[1][2]);
        float4 a = combine_half(sW, bs, half);
        float v = a.x * h1.x + a.y * h1.y + a.z * h1.z + a.w * h1.w;
        v += __shfl_xor_sync(mask, v, 1);
        if (half == 0) red_add_f32(&out[d2.y], v);
    }
}

// K5: out = elu(out) in place
__global__ void k_act2(float* __restrict__ out, int n_nodes) {
    int n = blockIdx.x * blockDim.x + threadIdx.x;
    if (n < n_nodes) out[n] = elu1(out[n]);
}

extern "C" void kernel_launch(void* const* d_in, const int* in_sizes, int n_in,
                              void* d_out, int out_size) {
    const float* x      = (const float*)d_in[0];
    const int*   ei     = (const int*)d_in[1];      // int32 (JAX x64 disabled)
    const float* pseudo = (const float*)d_in[2];
    const float* W1     = (const float*)d_in[3];
    const float* root1  = (const float*)d_in[4];
    const float* bias1  = (const float*)d_in[5];
    const float* W2     = (const float*)d_in[6];
    const float* root2  = (const float*)d_in[7];
    const float* bias2  = (const float*)d_in[8];
    float* out = (float*)d_out;

    int n_nodes = in_sizes[0];
    int n_edges = in_sizes[1] / 2;

    const int T = 256;
    // pair-cooperative: 2 lanes/edge, 2 edges/pair -> 1 thread per edge
    int n_pairs = (n_edges + 1) / 2;
    int eb = (2 * n_pairs + T - 1) / T;
    k_init_h<<<(n_nodes + T - 1) / T, T>>>(x, root1, bias1, n_nodes);
    k_edge1<<<eb, T>>>(ei, pseudo, x, W1, n_edges);
    k_act1<<<(n_nodes + T - 1) / T, T>>>(root2, bias2, out, n_nodes);
    k_edge2<<<eb, T>>>(ei, pseudo, W2, out, n_edges);
    k_act2<<<(n_nodes + T - 1) / T, T>>>(out, n_nodes);
}

// round 9
// speedup vs baseline: 1.3098x; 1.0252x over previous
#include <cuda_runtime.h>
#include <math.h>

#define HID 8
#define KSIZE 5
#define KK (KSIZE * KSIZE * KSIZE)   // 125
#define WSTRIDE 10                   // padded floats per cell -> spread bank groups

#define MAX_NODES 50000
__device__ __align__(16) float g_h[MAX_NODES * HID];

__device__ __forceinline__ void red_add_v4(float* addr, float4 v) {
    asm volatile("red.global.add.v4.f32 [%0], {%1,%2,%3,%4};"
                 :: "l"(addr), "f"(v.x), "f"(v.y), "f"(v.z), "f"(v.w) : "memory");
}
__device__ __forceinline__ void red_add_f32(float* addr, float v) {
    asm volatile("red.global.add.f32 [%0], %1;" :: "l"(addr), "f"(v) : "memory");
}

__device__ __forceinline__ float elu1(float v) {
    return v > 0.f ? v : expm1f(v);
}

struct Basis {
    int base;
    float w[8];
};

__device__ __forceinline__ Basis make_basis(float p0, float p1, float p2) {
    float pos0 = p0 * (KSIZE - 1), pos1 = p1 * (KSIZE - 1), pos2 = p2 * (KSIZE - 1);
    float f0 = fminf(fmaxf(floorf(pos0), 0.f), (float)(KSIZE - 2));
    float f1 = fminf(fmaxf(floorf(pos1), 0.f), (float)(KSIZE - 2));
    float f2 = fminf(fmaxf(floorf(pos2), 0.f), (float)(KSIZE - 2));
    float r0 = pos0 - f0, r1 = pos1 - f1, r2 = pos2 - f2;
    float u0 = 1.f - r0, u1 = 1.f - r1, u2 = 1.f - r2;
    Basis b;
    b.base = (int)f0 + KSIZE * (int)f1 + KSIZE * KSIZE * (int)f2;
    b.w[0] = u0 * u1 * u2;
    b.w[1] = r0 * u1 * u2;
    b.w[2] = u0 * r1 * u2;
    b.w[3] = r0 * r1 * u2;
    b.w[4] = u0 * u1 * r2;
    b.w[5] = r0 * u1 * r2;
    b.w[6] = u0 * r1 * r2;
    b.w[7] = r0 * r1 * r2;
    return b;
}

__constant__ int c_offs[8] = {0, 1, KSIZE, KSIZE + 1,
                              KSIZE * KSIZE, KSIZE * KSIZE + 1,
                              KSIZE * KSIZE + KSIZE, KSIZE * KSIZE + KSIZE + 1};

// Half-combine: this lane's 4 channels (half in {0,1}) of sum_b w_b * W[cell_b][:]
__device__ __forceinline__ float4 combine_half(const float* sW, const Basis& bs, int half) {
    float4 a = make_float4(0.f, 0.f, 0.f, 0.f);
    const float* sWh = sW + half * 4;
#pragma unroll
    for (int b = 0; b < 8; b++) {
        const float2* wp = (const float2*)&sWh[(bs.base + c_offs[b]) * WSTRIDE];
        float2 w0 = wp[0], w1 = wp[1];
        float wb = bs.w[b];
        a.x += wb * w0.x; a.y += wb * w0.y;
        a.z += wb * w1.x; a.w += wb * w1.y;
    }
    return a;
}

__device__ __forceinline__ void load_smem_w(float* sW, const float* W) {
    for (int i = threadIdx.x; i < KK * WSTRIDE; i += blockDim.x) {
        int cell = i / WSTRIDE, o = i - cell * WSTRIDE;
        sW[i] = (o < HID) ? W[cell * HID + o] : 0.f;
    }
    __syncthreads();
}

// K1: h_pre[n][o] = x[n] * root1[o] + bias1[o]
__global__ void k_init_h(const float* __restrict__ x,
                         const float* __restrict__ root1,
                         const float* __restrict__ bias1, int n_nodes) {
    int n = blockIdx.x * blockDim.x + threadIdx.x;
    if (n >= n_nodes) return;
    float xv = x[n];
    float4 r0 = *(const float4*)&root1[0];
    float4 r1 = *(const float4*)&root1[4];
    float4 b0 = *(const float4*)&bias1[0];
    float4 b1 = *(const float4*)&bias1[4];
    float4* hp = (float4*)&g_h[n * HID];
    hp[0] = make_float4(xv * r0.x + b0.x, xv * r0.y + b0.y, xv * r0.z + b0.z, xv * r0.w + b0.w);
    hp[1] = make_float4(xv * r1.x + b1.x, xv * r1.y + b1.y, xv * r1.z + b1.z, xv * r1.w + b1.w);
}

// K2: layer-1, pair-cooperative, 4 edges per pair. lane half=t&1 owns channels [half*4, half*4+4).
__global__ void __launch_bounds__(256, 5)
k_edge1(const int* __restrict__ ei,
        const float* __restrict__ pseudo,
        const float* __restrict__ x,
        const float* __restrict__ W1, int n_edges) {
    __shared__ __align__(16) float sW[KK * WSTRIDE];
    load_smem_w(sW, W1);

    int t = blockIdx.x * blockDim.x + threadIdx.x;
    int p = t >> 1, half = t & 1;
    int e0 = p * 4;
    if (e0 >= n_edges) return;

    int s[4], d[4];
    float pf[12];
    if (e0 + 4 <= n_edges) {
        int4 s4 = *(const int4*)&ei[e0];
        int4 d4 = *(const int4*)&ei[n_edges + e0];
        s[0] = s4.x; s[1] = s4.y; s[2] = s4.z; s[3] = s4.w;
        d[0] = d4.x; d[1] = d4.y; d[2] = d4.z; d[3] = d4.w;
        const float4* pp = (const float4*)&pseudo[3 * e0];
        float4 P0 = pp[0], P1 = pp[1], P2 = pp[2];
        pf[0]=P0.x; pf[1]=P0.y; pf[2]=P0.z; pf[3]=P0.w;
        pf[4]=P1.x; pf[5]=P1.y; pf[6]=P1.z; pf[7]=P1.w;
        pf[8]=P2.x; pf[9]=P2.y; pf[10]=P2.z; pf[11]=P2.w;
    } else {
        for (int k = 0; k < 4; k++) {
            int e = e0 + k;
            bool v = e < n_edges;
            s[k] = v ? ei[e] : 0;
            d[k] = v ? ei[n_edges + e] : 0;
            pf[3*k]   = v ? pseudo[3*e]   : 0.f;
            pf[3*k+1] = v ? pseudo[3*e+1] : 0.f;
            pf[3*k+2] = v ? pseudo[3*e+2] : 0.f;
        }
    }

    // front-batched gathers
    float xj[4];
#pragma unroll
    for (int k = 0; k < 4; k++) xj[k] = __ldg(&x[s[k]]);

    float4 a[4];
#pragma unroll
    for (int k = 0; k < 4; k++) {
        Basis bs = make_basis(pf[3*k], pf[3*k+1], pf[3*k+2]);
        a[k] = combine_half(sW, bs, half);
    }
#pragma unroll
    for (int k = 0; k < 4; k++) {
        if (e0 + k < n_edges)
            red_add_v4(&g_h[d[k] * HID + half * 4],
                       make_float4(xj[k] * a[k].x, xj[k] * a[k].y,
                                   xj[k] * a[k].z, xj[k] * a[k].w));
    }
}

// K3: h = elu(h_pre) in place; out_pre[n] = h . root2 + bias2
__global__ void k_act1(const float* __restrict__ root2,
                       const float* __restrict__ bias2,
                       float* __restrict__ out, int n_nodes) {
    int n = blockIdx.x * blockDim.x + threadIdx.x;
    if (n >= n_nodes) return;
    float4* hp = (float4*)&g_h[n * HID];
    float4 h0 = hp[0], h1 = hp[1];
    h0.x = elu1(h0.x); h0.y = elu1(h0.y); h0.z = elu1(h0.z); h0.w = elu1(h0.w);
    h1.x = elu1(h1.x); h1.y = elu1(h1.y); h1.z = elu1(h1.z); h1.w = elu1(h1.w);
    hp[0] = h0; hp[1] = h1;
    float4 r0 = *(const float4*)&root2[0];
    float4 r1 = *(const float4*)&root2[4];
    float acc = bias2[0]
              + h0.x * r0.x + h0.y * r0.y + h0.z * r0.z + h0.w * r0.w
              + h1.x * r1.x + h1.y * r1.y + h1.z * r1.z + h1.w * r1.w;
    out[n] = acc;
}

// K4: layer-2, pair-cooperative, 4 edges per pair; front-batched 16B gathers.
__global__ void __launch_bounds__(256, 5)
k_edge2(const int* __restrict__ ei,
        const float* __restrict__ pseudo,
        const float* __restrict__ W2,
        float* __restrict__ out, int n_edges) {
    __shared__ __align__(16) float sW[KK * WSTRIDE];
    load_smem_w(sW, W2);

    int t = blockIdx.x * blockDim.x + threadIdx.x;
    int p = t >> 1, half = t & 1;
    int e0 = p * 4;
    if (e0 >= n_edges) return;

    int s[4], d[4];
    float pf[12];
    if (e0 + 4 <= n_edges) {
        int4 s4 = *(const int4*)&ei[e0];
        int4 d4 = *(const int4*)&ei[n_edges + e0];
        s[0] = s4.x; s[1] = s4.y; s[2] = s4.z; s[3] = s4.w;
        d[0] = d4.x; d[1] = d4.y; d[2] = d4.z; d[3] = d4.w;
        const float4* pp = (const float4*)&pseudo[3 * e0];
        float4 P0 = pp[0], P1 = pp[1], P2 = pp[2];
        pf[0]=P0.x; pf[1]=P0.y; pf[2]=P0.z; pf[3]=P0.w;
        pf[4]=P1.x; pf[5]=P1.y; pf[6]=P1.z; pf[7]=P1.w;
        pf[8]=P2.x; pf[9]=P2.y; pf[10]=P2.z; pf[11]=P2.w;
    } else {
        for (int k = 0; k < 4; k++) {
            int e = e0 + k;
            bool v = e < n_edges;
            s[k] = v ? ei[e] : 0;
            d[k] = v ? ei[n_edges + e] : 0;
            pf[3*k]   = v ? pseudo[3*e]   : 0.f;
            pf[3*k+1] = v ? pseudo[3*e+1] : 0.f;
            pf[3*k+2] = v ? pseudo[3*e+2] : 0.f;
        }
    }

    // front-batched scattered 16B gathers (this lane's half of h[src])
    float4 hh[4];
#pragma unroll
    for (int k = 0; k < 4; k++)
        hh[k] = *(const float4*)&g_h[s[k] * HID + half * 4];

    float v[4];
#pragma unroll
    for (int k = 0; k < 4; k++) {
        Basis bs = make_basis(pf[3*k], pf[3*k+1], pf[3*k+2]);
        float4 a = combine_half(sW, bs, half);
        v[k] = a.x * hh[k].x + a.y * hh[k].y + a.z * hh[k].z + a.w * hh[k].w;
    }

    unsigned mask = __activemask();
#pragma unroll
    for (int k = 0; k < 4; k++)
        v[k] += __shfl_xor_sync(mask, v[k], 1);

    if (half == 0) {
#pragma unroll
        for (int k = 0; k < 4; k++)
            if (e0 + k < n_edges) red_add_f32(&out[d[k]], v[k]);
    }
}

// K5: out = elu(out) in place
__global__ void k_act2(float* __restrict__ out, int n_nodes) {
    int n = blockIdx.x * blockDim.x + threadIdx.x;
    if (n < n_nodes) out[n] = elu1(out[n]);
}

extern "C" void kernel_launch(void* const* d_in, const int* in_sizes, int n_in,
                              void* d_out, int out_size) {
    const float* x      = (const float*)d_in[0];
    const int*   ei     = (const int*)d_in[1];      // int32 (JAX x64 disabled)
    const float* pseudo = (const float*)d_in[2];
    const float* W1     = (const float*)d_in[3];
    const float* root1  = (const float*)d_in[4];
    const float* bias1  = (const float*)d_in[5];
    const float* W2     = (const float*)d_in[6];
    const float* root2  = (const float*)d_in[7];
    const float* bias2  = (const float*)d_in[8];
    float* out = (float*)d_out;

    int n_nodes = in_sizes[0];
    int n_edges = in_sizes[1] / 2;

    const int T = 256;
    // pair-cooperative: 2 lanes/pair, 4 edges/pair
    int n_pairs = (n_edges + 3) / 4;
    int eb = (2 * n_pairs + T - 1) / T;
    k_init_h<<<(n_nodes + T - 1) / T, T>>>(x, root1, bias1, n_nodes);
    k_edge1<<<eb, T>>>(ei, pseudo, x, W1, n_edges);
    k_act1<<<(n_nodes + T - 1) / T, T>>>(root2, bias2, out, n_nodes);
    k_edge2<<<eb, T>>>(ei, pseudo, W2, out, n_edges);
    k_act2<<<(n_nodes + T - 1) / T, T>>>(out, n_nodes);
}

// round 10
// speedup vs baseline: 1.7307x; 1.3213x over previous
#include <cuda_runtime.h>
#include <cuda_fp16.h>
#include <math.h>

#define HID 8
#define KSIZE 5
#define KK (KSIZE * KSIZE * KSIZE)   // 125
#define HSTRIDE 20                   // halfs per cell (40B): 8B-aligned half-rows, spread banks

#define MAX_NODES 50000
__device__ __align__(16) float g_h[MAX_NODES * HID];

__device__ __forceinline__ void red_add_v4(float* addr, float4 v) {
    asm volatile("red.global.add.v4.f32 [%0], {%1,%2,%3,%4};"
                 :: "l"(addr), "f"(v.x), "f"(v.y), "f"(v.z), "f"(v.w) : "memory");
}
__device__ __forceinline__ void red_add_f32(float* addr, float v) {
    asm volatile("red.global.add.f32 [%0], %1;" :: "l"(addr), "f"(v) : "memory");
}

__device__ __forceinline__ float elu1(float v) {
    return v > 0.f ? v : expm1f(v);
}

struct Basis {
    int base;
    float w[8];
};

__device__ __forceinline__ Basis make_basis(float p0, float p1, float p2) {
    float pos0 = p0 * (KSIZE - 1), pos1 = p1 * (KSIZE - 1), pos2 = p2 * (KSIZE - 1);
    float f0 = fminf(fmaxf(floorf(pos0), 0.f), (float)(KSIZE - 2));
    float f1 = fminf(fmaxf(floorf(pos1), 0.f), (float)(KSIZE - 2));
    float f2 = fminf(fmaxf(floorf(pos2), 0.f), (float)(KSIZE - 2));
    float r0 = pos0 - f0, r1 = pos1 - f1, r2 = pos2 - f2;
    float u0 = 1.f - r0, u1 = 1.f - r1, u2 = 1.f - r2;
    Basis b;
    b.base = (int)f0 + KSIZE * (int)f1 + KSIZE * KSIZE * (int)f2;
    b.w[0] = u0 * u1 * u2;
    b.w[1] = r0 * u1 * u2;
    b.w[2] = u0 * r1 * u2;
    b.w[3] = r0 * r1 * u2;
    b.w[4] = u0 * u1 * r2;
    b.w[5] = r0 * u1 * r2;
    b.w[6] = u0 * r1 * r2;
    b.w[7] = r0 * r1 * r2;
    return b;
}

__constant__ int c_offs[8] = {0, 1, KSIZE, KSIZE + 1,
                              KSIZE * KSIZE, KSIZE * KSIZE + 1,
                              KSIZE * KSIZE + KSIZE, KSIZE * KSIZE + KSIZE + 1};

// Half-combine from fp16 table: lane's 4 channels (half in {0,1}) of sum_b w_b * W[cell_b][:]
// One 8B LDS.64 per corner.
__device__ __forceinline__ float4 combine_half(const __half* sH, const Basis& bs, int half) {
    float4 a = make_float4(0.f, 0.f, 0.f, 0.f);
    const __half* sHh = sH + half * 4;
#pragma unroll
    for (int b = 0; b < 8; b++) {
        __half2 raw2[2];
        *(uint2*)raw2 = *(const uint2*)&sHh[(bs.base + c_offs[b]) * HSTRIDE];
        float2 f01 = __half22float2(raw2[0]);
        float2 f23 = __half22float2(raw2[1]);
        float wb = bs.w[b];
        a.x += wb * f01.x; a.y += wb * f01.y;
        a.z += wb * f23.x; a.w += wb * f23.y;
    }
    return a;
}

__device__ __forceinline__ void load_smem_w(__half* sH, const float* W) {
    for (int i = threadIdx.x; i < KK * HSTRIDE; i += blockDim.x) {
        int cell = i / HSTRIDE, o = i - cell * HSTRIDE;
        sH[i] = __float2half((o < HID) ? W[cell * HID + o] : 0.f);
    }
    __syncthreads();
}

// K1: h_pre[n][o] = x[n] * root1[o] + bias1[o]
__global__ void k_init_h(const float* __restrict__ x,
                         const float* __restrict__ root1,
                         const float* __restrict__ bias1, int n_nodes) {
    int n = blockIdx.x * blockDim.x + threadIdx.x;
    if (n >= n_nodes) return;
    float xv = x[n];
    float4 r0 = *(const float4*)&root1[0];
    float4 r1 = *(const float4*)&root1[4];
    float4 b0 = *(const float4*)&bias1[0];
    float4 b1 = *(const float4*)&bias1[4];
    float4* hp = (float4*)&g_h[n * HID];
    hp[0] = make_float4(xv * r0.x + b0.x, xv * r0.y + b0.y, xv * r0.z + b0.z, xv * r0.w + b0.w);
    hp[1] = make_float4(xv * r1.x + b1.x, xv * r1.y + b1.y, xv * r1.z + b1.z, xv * r1.w + b1.w);
}

// K2: layer-1, pair-cooperative, 4 edges per pair. lane half=t&1 owns channels [half*4, half*4+4).
__global__ void __launch_bounds__(256, 5)
k_edge1(const int* __restrict__ ei,
        const float* __restrict__ pseudo,
        const float* __restrict__ x,
        const float* __restrict__ W1, int n_edges) {
    __shared__ __align__(16) __half sH[KK * HSTRIDE];
    load_smem_w(sH, W1);

    int t = blockIdx.x * blockDim.x + threadIdx.x;
    int p = t >> 1, half = t & 1;
    int e0 = p * 4;
    if (e0 >= n_edges) return;

    int s[4], d[4];
    float pf[12];
    if (e0 + 4 <= n_edges) {
        int4 s4 = *(const int4*)&ei[e0];
        int4 d4 = *(const int4*)&ei[n_edges + e0];
        s[0] = s4.x; s[1] = s4.y; s[2] = s4.z; s[3] = s4.w;
        d[0] = d4.x; d[1] = d4.y; d[2] = d4.z; d[3] = d4.w;
        const float4* pp = (const float4*)&pseudo[3 * e0];
        float4 P0 = pp[0], P1 = pp[1], P2 = pp[2];
        pf[0]=P0.x; pf[1]=P0.y; pf[2]=P0.z; pf[3]=P0.w;
        pf[4]=P1.x; pf[5]=P1.y; pf[6]=P1.z; pf[7]=P1.w;
        pf[8]=P2.x; pf[9]=P2.y; pf[10]=P2.z; pf[11]=P2.w;
    } else {
        for (int k = 0; k < 4; k++) {
            int e = e0 + k;
            bool v = e < n_edges;
            s[k] = v ? ei[e] : 0;
            d[k] = v ? ei[n_edges + e] : 0;
            pf[3*k]   = v ? pseudo[3*e]   : 0.f;
            pf[3*k+1] = v ? pseudo[3*e+1] : 0.f;
            pf[3*k+2] = v ? pseudo[3*e+2] : 0.f;
        }
    }

    float xj[4];
#pragma unroll
    for (int k = 0; k < 4; k++) xj[k] = __ldg(&x[s[k]]);

    float4 a[4];
#pragma unroll
    for (int k = 0; k < 4; k++) {
        Basis bs = make_basis(pf[3*k], pf[3*k+1], pf[3*k+2]);
        a[k] = combine_half(sH, bs, half);
    }
#pragma unroll
    for (int k = 0; k < 4; k++) {
        if (e0 + k < n_edges)
            red_add_v4(&g_h[d[k] * HID + half * 4],
                       make_float4(xj[k] * a[k].x, xj[k] * a[k].y,
                                   xj[k] * a[k].z, xj[k] * a[k].w));
    }
}

// K3: h = elu(h_pre) in place; out_pre[n] = h . root2 + bias2
__global__ void k_act1(const float* __restrict__ root2,
                       const float* __restrict__ bias2,
                       float* __restrict__ out, int n_nodes) {
    int n = blockIdx.x * blockDim.x + threadIdx.x;
    if (n >= n_nodes) return;
    float4* hp = (float4*)&g_h[n * HID];
    float4 h0 = hp[0], h1 = hp[1];
    h0.x = elu1(h0.x); h0.y = elu1(h0.y); h0.z = elu1(h0.z); h0.w = elu1(h0.w);
    h1.x = elu1(h1.x); h1.y = elu1(h1.y); h1.z = elu1(h1.z); h1.w = elu1(h1.w);
    hp[0] = h0; hp[1] = h1;
    float4 r0 = *(const float4*)&root2[0];
    float4 r1 = *(const float4*)&root2[4];
    float acc = bias2[0]
              + h0.x * r0.x + h0.y * r0.y + h0.z * r0.z + h0.w * r0.w
              + h1.x * r1.x + h1.y * r1.y + h1.z * r1.z + h1.w * r1.w;
    out[n] = acc;
}

// K4: layer-2, pair-cooperative, 4 edges per pair; front-batched 16B gathers.
__global__ void __launch_bounds__(256, 5)
k_edge2(const int* __restrict__ ei,
        const float* __restrict__ pseudo,
        const float* __restrict__ W2,
        float* __restrict__ out, int n_edges) {
    __shared__ __align__(16) __half sH[KK * HSTRIDE];
    load_smem_w(sH, W2);

    int t = blockIdx.x * blockDim.x + threadIdx.x;
    int p = t >> 1, half = t & 1;
    int e0 = p * 4;
    if (e0 >= n_edges) return;

    int s[4], d[4];
    float pf[12];
    if (e0 + 4 <= n_edges) {
        int4 s4 = *(const int4*)&ei[e0];
        int4 d4 = *(const int4*)&ei[n_edges + e0];
        s[0] = s4.x; s[1] = s4.y; s[2] = s4.z; s[3] = s4.w;
        d[0] = d4.x; d[1] = d4.y; d[2] = d4.z; d[3] = d4.w;
        const float4* pp = (const float4*)&pseudo[3 * e0];
        float4 P0 = pp[0], P1 = pp[1], P2 = pp[2];
        pf[0]=P0.x; pf[1]=P0.y; pf[2]=P0.z; pf[3]=P0.w;
        pf[4]=P1.x; pf[5]=P1.y; pf[6]=P1.z; pf[7]=P1.w;
        pf[8]=P2.x; pf[9]=P2.y; pf[10]=P2.z; pf[11]=P2.w;
    } else {
        for (int k = 0; k < 4; k++) {
            int e = e0 + k;
            bool v = e < n_edges;
            s[k] = v ? ei[e] : 0;
            d[k] = v ? ei[n_edges + e] : 0;
            pf[3*k]   = v ? pseudo[3*e]   : 0.f;
            pf[3*k+1] = v ? pseudo[3*e+1] : 0.f;
            pf[3*k+2] = v ? pseudo[3*e+2] : 0.f;
        }
    }

    // front-batched scattered 16B gathers (this lane's half of h[src])
    float4 hh[4];
#pragma unroll
    for (int k = 0; k < 4; k++)
        hh[k] = *(const float4*)&g_h[s[k] * HID + half * 4];

    float v[4];
#pragma unroll
    for (int k = 0; k < 4; k++) {
        Basis bs = make_basis(pf[3*k], pf[3*k+1], pf[3*k+2]);
        float4 a = combine_half(sH, bs, half);
        v[k] = a.x * hh[k].x + a.y * hh[k].y + a.z * hh[k].z + a.w * hh[k].w;
    }

    unsigned mask = __activemask();
#pragma unroll
    for (int k = 0; k < 4; k++)
        v[k] += __shfl_xor_sync(mask, v[k], 1);

    if (half == 0) {
#pragma unroll
        for (int k = 0; k < 4; k++)
            if (e0 + k < n_edges) red_add_f32(&out[d[k]], v[k]);
    }
}

// K5: out = elu(out) in place
__global__ void k_act2(float* __restrict__ out, int n_nodes) {
    int n = blockIdx.x * blockDim.x + threadIdx.x;
    if (n < n_nodes) out[n] = elu1(out[n]);
}

extern "C" void kernel_launch(void* const* d_in, const int* in_sizes, int n_in,
                              void* d_out, int out_size) {
    const float* x      = (const float*)d_in[0];
    const int*   ei     = (const int*)d_in[1];      // int32 (JAX x64 disabled)
    const float* pseudo = (const float*)d_in[2];
    const float* W1     = (const float*)d_in[3];
    const float* root1  = (const float*)d_in[4];
    const float* bias1  = (const float*)d_in[5];
    const float* W2     = (const float*)d_in[6];
    const float* root2  = (const float*)d_in[7];
    const float* bias2  = (const float*)d_in[8];
    float* out = (float*)d_out;

    int n_nodes = in_sizes[0];
    int n_edges = in_sizes[1] / 2;

    const int T = 256;
    int n_pairs = (n_edges + 3) / 4;
    int eb = (2 * n_pairs + T - 1) / T;
    k_init_h<<<(n_nodes + T - 1) / T, T>>>(x, root1, bias1, n_nodes);
    k_edge1<<<eb, T>>>(ei, pseudo, x, W1, n_edges);
    k_act1<<<(n_nodes + T - 1) / T, T>>>(root2, bias2, out, n_nodes);
    k_edge2<<<eb, T>>>(ei, pseudo, W2, out, n_edges);
    k_act2<<<(n_nodes + T - 1) / T, T>>>(out, n_nodes);
}